// round 4
// baseline (speedup 1.0000x reference)
#include <cuda_runtime.h>

#define G   16
#define Bsz 2
#define C   256
#define Cg  16
#define HW  576     // 24*24
#define AC  6400    // 25*C
#define EPSI 1e-5f

typedef unsigned long long ull;

// Scratch (device globals — no allocation allowed)
__device__ float g_h1[G*Bsz*C*HW];     // (i,b,c,hw)  18.9 MB
__device__ float g_pooled[G*Bsz*AC];   // (i,b,ac)
__device__ float g_aff[G*Bsz*G];       // aff_i[i,b,l]

// ---- packed f32x2 helpers (sm_103a FFMA2 path, not emitted by ptxas from C++) ----
__device__ __forceinline__ ull pack2(float lo, float hi) {
    ull r; asm("mov.b64 %0, {%1,%2};" : "=l"(r) : "f"(lo), "f"(hi)); return r;
}
__device__ __forceinline__ void unpack2(ull v, float& lo, float& hi) {
    asm("mov.b64 {%0,%1}, %2;" : "=f"(lo), "=f"(hi) : "l"(v));
}
__device__ __forceinline__ ull fma2(ull a, ull b, ull c) {
    ull d; asm("fma.rn.f32x2 %0, %1, %2, %3;" : "=l"(d) : "l"(a), "l"(b), "l"(c));
    return d;
}

// ---------------------------------------------------------------------------
// Fused kernel: conv1(3x3 grouped)+BN+ReLU -> smem+gmem, then conv2(1x1,pad=1)
// +BN+ReLU+26x26-mean -> g_pooled.  Block = (i, b, group k), 192 threads.
//
// Dynamic smem layout (floats):
//   xt  [16][26*26]  padded conv1 input tile (zero border)   10816
//   h1s [16][576]    conv1 output (BN+ReLU applied)           9216
//   wsh [144*16]     conv1 weights, layout [(cin*9+tap)*16+o] 2304
// total 22336 floats = 89344 bytes
// ---------------------------------------------------------------------------
__global__ __launch_bounds__(192, 2) void fused_conv_kernel(
    const float* __restrict__ x,  const float* __restrict__ W1,
    const float* __restrict__ g1, const float* __restrict__ b1,
    const float* __restrict__ m1, const float* __restrict__ v1,
    const float* __restrict__ W2, const float* __restrict__ g2,
    const float* __restrict__ b2, const float* __restrict__ m2,
    const float* __restrict__ v2)
{
    extern __shared__ __align__(16) float smem[];
    float* xt  = smem;            // 16 x 676 (padded 26x26)
    float* h1s = smem + 10816;    // 16 x 576
    float* wsh = smem + 20032;    // 2304

    const int bid = blockIdx.x;
    const int i = bid >> 5, b = (bid >> 4) & 1, k = bid & 15;
    const int tid = threadIdx.x, lane = tid & 31, warp = tid >> 5;

    // ---- phase 0: zero padded tile ----
    float4* xt4 = (float4*)xt;
    for (int idx = tid; idx < 2704; idx += 192)
        xt4[idx] = make_float4(0.f, 0.f, 0.f, 0.f);
    __syncthreads();

    // ---- load x interior + transposed conv1 weights ----
    const float* xsrc = x + (b*C + k*16)*HW;            // 16 contiguous channels
    for (int idx = tid; idx < 16*HW; idx += 192) {
        int c = idx / HW, rem = idx - c*HW;
        int y = rem / 24, xx = rem - y*24;
        xt[c*676 + (y + 1)*26 + (xx + 1)] = xsrc[idx];
    }
    const float* wsrc = W1 + (i*C + k*16)*144;          // 2304 contiguous floats
    for (int idx = tid; idx < 2304; idx += 192) {
        int o = idx / 144, r = idx - o*144;             // r = cin*9 + tap
        wsh[r*16 + o] = wsrc[idx];
    }
    __syncthreads();

    // ---- phase 1: conv1, 3 pixels x 16 out-channels per thread ----
    ull acc2[3][8];
    #pragma unroll
    for (int j = 0; j < 3; j++)
        #pragma unroll
        for (int op = 0; op < 8; op++) acc2[j][op] = 0ull;

    int p[3], pb[3];
    #pragma unroll
    for (int j = 0; j < 3; j++) {
        p[j] = tid + j*192;                 // all < 576
        int py = p[j] / 24, px = p[j] - py*24;
        pb[j] = py*26 + px;                 // padded base: tap (dy,dx) at +dy*26+dx
    }

    for (int cin = 0; cin < 16; cin++) {
        const float* tc = xt + cin*676;
        #pragma unroll
        for (int dy = 0; dy < 3; dy++) {
            #pragma unroll
            for (int dx = 0; dx < 3; dx++) {
                ull xp[3];
                #pragma unroll
                for (int j = 0; j < 3; j++) {
                    float xv = tc[pb[j] + dy*26 + dx];   // immediate-offset LDS
                    xp[j] = pack2(xv, xv);
                }
                const ull* wrow = (const ull*)&wsh[(cin*9 + dy*3 + dx)*16];
                #pragma unroll
                for (int op = 0; op < 8; op++) {
                    ull wv = wrow[op];                   // broadcast LDS.64
                    #pragma unroll
                    for (int j = 0; j < 3; j++)
                        acc2[j][op] = fma2(xp[j], wv, acc2[j][op]);
                }
            }
        }
    }

    // ---- conv1 epilogue: BN + ReLU -> h1s (smem) + g_h1 (gmem) ----
    float* dst = g_h1 + ((i*Bsz + b)*C + k*16)*HW;
    #pragma unroll
    for (int op = 0; op < 8; op++) {
        float a0[3], a1[3];
        #pragma unroll
        for (int j = 0; j < 3; j++) unpack2(acc2[j][op], a0[j], a1[j]);
        #pragma unroll
        for (int half = 0; half < 2; half++) {
            const int o = op*2 + half;
            const int pi = i*C + k*16 + o;
            const float s  = g1[pi] * rsqrtf(v1[pi] + EPSI);
            const float cc = fmaf(-m1[pi], s, b1[pi]);
            #pragma unroll
            for (int j = 0; j < 3; j++) {
                float av = half ? a1[j] : a0[j];
                float y = fmaxf(fmaf(av, s, cc), 0.f);
                h1s[o*HW + p[j]] = y;
                dst[o*HW + p[j]] = y;
            }
        }
    }
    __syncthreads();

    // ---- phase 2: 1x1 conv (pad=1) + BN + ReLU + spatial mean ----
    float* pooled = g_pooled + (i*Bsz + b)*AC + k*400;

    for (int cb = warp*4; cb < 400; cb += 24) {           // 6 warps x 4 channels
        ull w2[4][16], s2[4], c2[4];
        float cj[4];
        #pragma unroll
        for (int j = 0; j < 4; j++) {
            const int pi = i*AC + k*400 + cb + j;
            const float* wp = W2 + pi*16;
            #pragma unroll
            for (int cin = 0; cin < 16; cin++) {
                float wv = wp[cin];
                w2[j][cin] = pack2(wv, wv);
            }
            float sc = g2[pi] * rsqrtf(v2[pi] + EPSI);
            float cc = fmaf(-m2[pi], sc, b2[pi]);          // b - m*s
            cj[j] = cc;
            s2[j] = pack2(sc, sc);
            c2[j] = pack2(cc, cc);
        }

        float acc[4] = {0.f, 0.f, 0.f, 0.f};
        #pragma unroll 3
        for (int it = 0; it < 9; it++) {                   // 288 pairs / 32 lanes
            const int pp2 = (lane + it*32) * 2;
            ull d2[4] = {0ull, 0ull, 0ull, 0ull};
            #pragma unroll
            for (int cin = 0; cin < 16; cin++) {
                ull xv = *(const ull*)&h1s[cin*HW + pp2];  // LDS.64, conflict-free
                #pragma unroll
                for (int j = 0; j < 4; j++)
                    d2[j] = fma2(xv, w2[j][cin], d2[j]);
            }
            #pragma unroll
            for (int j = 0; j < 4; j++) {
                ull t = fma2(d2[j], s2[j], c2[j]);         // BN, both pixels
                float lo, hi; unpack2(t, lo, hi);
                acc[j] += fmaxf(lo, 0.f) + fmaxf(hi, 0.f); // ReLU + pool accum
            }
        }
        #pragma unroll
        for (int j = 0; j < 4; j++) {
            float a = acc[j];
            #pragma unroll
            for (int off = 16; off; off >>= 1)
                a += __shfl_xor_sync(0xffffffffu, a, off);
            if (lane == 0) {
                // 100 border pixels of the (pad=1) 26x26 conv output
                float border = 100.f * fmaxf(cj[j], 0.f);
                pooled[cb + j] = (a + border) * (1.f / 676.f);
            }
        }
    }
}

// ---------------------------------------------------------------------------
// aff_i[i,b,l] = <pooled[i,b,i*400:..], pooled[i,b,l*400:..]>/16
// One warp per (i,b,l).
// ---------------------------------------------------------------------------
__global__ __launch_bounds__(256) void aff_kernel()
{
    const int gw = blockIdx.x*8 + (threadIdx.x >> 5);   // 0..511
    const int lane = threadIdx.x & 31;
    const int i = gw >> 5, b = (gw >> 4) & 1, l = gw & 15;
    const float* base = g_pooled + (i*Bsz + b)*AC;
    const float* pa = base + i*400;
    const float* pb = base + l*400;
    float s = 0.f;
    #pragma unroll
    for (int m3 = lane; m3 < 400; m3 += 32)
        s = fmaf(pa[m3], pb[m3], s);
    #pragma unroll
    for (int off = 16; off; off >>= 1)
        s += __shfl_xor_sync(0xffffffffu, s, off);
    if (lane == 0) g_aff[(i*Bsz + b)*G + l] = s * (1.f / 16.f);
}

// ---------------------------------------------------------------------------
// z[i,p,q,cg,hw] = sum_k aff_i[i,p,k] * h1[i,q,k*16+cg,hw]
// Each thread produces BOTH p outputs from one set of h1 loads.
// ---------------------------------------------------------------------------
__global__ __launch_bounds__(256) void out_kernel(float* __restrict__ out)
{
    const int idx = blockIdx.x*256 + threadIdx.x;
    if (idx >= 512*HW) return;
    const int pix = idx % HW;
    const int ch  = idx / HW;                 // 0..511
    const int i = ch >> 5, q = (ch >> 4) & 1, cg = ch & 15;

    const float* a0 = g_aff + (i*Bsz + 0)*G;              // warp-uniform
    const float* a1 = g_aff + (i*Bsz + 1)*G;
    const float* h  = g_h1 + ((i*Bsz + q)*C + cg)*HW + pix;  // coalesced over pix
    float s0 = 0.f, s1 = 0.f;
    #pragma unroll
    for (int kk = 0; kk < 16; kk++) {
        float hv = __ldg(h + kk*16*HW);
        s0 = fmaf(a0[kk], hv, s0);
        s1 = fmaf(a1[kk], hv, s1);
    }
    out[ch*HW + pix]            = s0;   // p = 0
    out[512*HW + ch*HW + pix]   = s1;   // p = 1
}

// ---------------------------------------------------------------------------
extern "C" void kernel_launch(void* const* d_in, const int* in_sizes, int n_in,
                              void* d_out, int out_size)
{
    const float* x  = (const float*)d_in[0];
    const float* W1 = (const float*)d_in[1];
    const float* g1 = (const float*)d_in[2];
    const float* b1 = (const float*)d_in[3];
    const float* m1 = (const float*)d_in[4];
    const float* v1 = (const float*)d_in[5];
    const float* W2 = (const float*)d_in[6];
    const float* g2 = (const float*)d_in[7];
    const float* b2 = (const float*)d_in[8];
    const float* m2 = (const float*)d_in[9];
    const float* v2 = (const float*)d_in[10];
    float* out = (float*)d_out;

    const int smem_bytes = 22336 * 4;   // 89344 B
    cudaFuncSetAttribute(fused_conv_kernel,
                         cudaFuncAttributeMaxDynamicSharedMemorySize, smem_bytes);

    fused_conv_kernel<<<512, 192, smem_bytes>>>(x, W1, g1, b1, m1, v1,
                                                W2, g2, b2, m2, v2);
    aff_kernel<<<64, 256>>>();
    out_kernel<<<(512*HW + 255)/256, 256>>>(out);
}

// round 7
// speedup vs baseline: 1.1511x; 1.1511x over previous
#include <cuda_runtime.h>

#define G   16
#define Bsz 2
#define C   256
#define Cg  16
#define HW  576     // 24*24
#define AC  6400    // 25*C
#define EPSI 1e-5f

typedef unsigned long long ull;

// Scratch (device globals — no allocation allowed)
__device__ float g_h1[G*Bsz*C*HW];     // (i,b,c,hw)  18.9 MB (L2-resident)
__device__ float g_pooled[G*Bsz*AC];   // (i,b,ac)
__device__ float g_aff[G*Bsz*G];       // aff_i[i,b,l]

// ---- packed f32x2 helpers (sm_103a FFMA2 path, not emitted by ptxas from C++) ----
__device__ __forceinline__ ull pack2(float lo, float hi) {
    ull r; asm("mov.b64 %0, {%1,%2};" : "=l"(r) : "f"(lo), "f"(hi)); return r;
}
__device__ __forceinline__ void unpack2(ull v, float& lo, float& hi) {
    asm("mov.b64 {%0,%1}, %2;" : "=f"(lo), "=f"(hi) : "l"(v));
}
__device__ __forceinline__ ull fma2(ull a, ull b, ull c) {
    ull d; asm("fma.rn.f32x2 %0, %1, %2, %3;" : "=l"(d) : "l"(a), "l"(b), "l"(c));
    return d;
}

// ---------------------------------------------------------------------------
// Kernel 1: 16x grouped 3x3 conv + BN + ReLU -> g_h1
// Block = (i, b, group k, oc-half h): 1024 blocks, 8 out-channels each.
// Padded 26x26 input tile (zero border) -> no predication, immediate-offset
// LDS. 3 pixels x 8 oc per thread. ~60 regs -> 4 blocks/SM = 24 warps/SM.
// ---------------------------------------------------------------------------
__global__ __launch_bounds__(192, 4) void conv1_kernel(
    const float* __restrict__ x,  const float* __restrict__ W1,
    const float* __restrict__ g1, const float* __restrict__ b1,
    const float* __restrict__ m1, const float* __restrict__ v1)
{
    __shared__ __align__(16) float xt[16*676];        // padded 26x26, 43264 B
    __shared__ __align__(8)  float wsh[144*8];        // [(cin*9+tap)*8 + o]
    const int bid = blockIdx.x;
    const int i = bid >> 6, b = (bid >> 5) & 1, k = (bid >> 1) & 15, h = bid & 1;
    const int tid = threadIdx.x;

    // zero padded tile
    float4* xt4 = (float4*)xt;
    for (int idx = tid; idx < 2704; idx += 192)
        xt4[idx] = make_float4(0.f, 0.f, 0.f, 0.f);
    __syncthreads();

    const float* xsrc = x + (b*C + k*16)*HW;          // 16 contiguous channels
    for (int idx = tid; idx < 16*HW; idx += 192) {
        int c = idx / HW, rem = idx - c*HW;
        int y = rem / 24, xx = rem - y*24;
        xt[c*676 + (y + 1)*26 + (xx + 1)] = xsrc[idx];
    }
    const float* wsrc = W1 + (i*C + k*16 + h*8)*144;  // 1152 contiguous floats
    for (int idx = tid; idx < 1152; idx += 192) {
        int o = idx / 144, r = idx - o*144;           // r = cin*9 + tap
        wsh[r*8 + o] = wsrc[idx];
    }
    __syncthreads();

    ull acc2[3][4];
    #pragma unroll
    for (int j = 0; j < 3; j++)
        #pragma unroll
        for (int op = 0; op < 4; op++) acc2[j][op] = 0ull;

    int p[3], pb[3];
    #pragma unroll
    for (int j = 0; j < 3; j++) {
        p[j] = tid + j*192;                 // all < 576
        int py = p[j] / 24, px = p[j] - py*24;
        pb[j] = py*26 + px;                 // padded base
    }

    for (int cin = 0; cin < 16; cin++) {
        const float* tc = xt + cin*676;
        #pragma unroll
        for (int dy = 0; dy < 3; dy++) {
            #pragma unroll
            for (int dx = 0; dx < 3; dx++) {
                ull xp[3];
                #pragma unroll
                for (int j = 0; j < 3; j++) {
                    float xv = tc[pb[j] + dy*26 + dx];   // immediate-offset LDS
                    xp[j] = pack2(xv, xv);
                }
                const ull* wrow = (const ull*)&wsh[(cin*9 + dy*3 + dx)*8];
                #pragma unroll
                for (int op = 0; op < 4; op++) {
                    ull wv = wrow[op];                   // broadcast LDS.64
                    #pragma unroll
                    for (int j = 0; j < 3; j++)
                        acc2[j][op] = fma2(xp[j], wv, acc2[j][op]);
                }
            }
        }
    }

    float* dst = g_h1 + ((i*Bsz + b)*C + k*16 + h*8)*HW;
    #pragma unroll
    for (int op = 0; op < 4; op++) {
        float a0[3], a1[3];
        #pragma unroll
        for (int j = 0; j < 3; j++) unpack2(acc2[j][op], a0[j], a1[j]);
        #pragma unroll
        for (int half = 0; half < 2; half++) {
            const int o = op*2 + half;
            const int pi = i*C + k*16 + h*8 + o;
            const float s  = g1[pi] * rsqrtf(v1[pi] + EPSI);
            const float cc = fmaf(-m1[pi], s, b1[pi]);
            #pragma unroll
            for (int j = 0; j < 3; j++) {
                float av = half ? a1[j] : a0[j];
                dst[o*HW + p[j]] = fmaxf(fmaf(av, s, cc), 0.f);
            }
        }
    }
}

// ---------------------------------------------------------------------------
// Kernel 2: fused 1x1 grouped conv (pad=1!) + BN + ReLU + 26x26 spatial mean.
// Block = (i, b, k, channel-half): 1024 blocks x 200 channels. h1 tile (reads
// hit L2) in smem; lane owns a PIXEL PAIR (LDS.64) vs 4 output channels with
// (w,w)-packed register weights -> 16 LDS.64 : 64 FFMA2 per 4096 MACs.
// ---------------------------------------------------------------------------
__global__ __launch_bounds__(128) void conv2_pool_kernel(
    const float* __restrict__ W2, const float* __restrict__ g2,
    const float* __restrict__ b2, const float* __restrict__ m2,
    const float* __restrict__ v2)
{
    __shared__ __align__(8) float tile[16*HW];     // 36 KB
    const int bid = blockIdx.x;
    const int i = bid >> 6, b = (bid >> 5) & 1, k = (bid >> 1) & 15, hh = bid & 1;
    const int tid = threadIdx.x, lane = tid & 31, warp = tid >> 5;

    const float* src = g_h1 + ((i*Bsz + b)*C + k*16)*HW;  // contiguous 9216 floats
    for (int idx = tid; idx < 16*HW; idx += 128) tile[idx] = src[idx];
    __syncthreads();

    float* pooled = g_pooled + (i*Bsz + b)*AC + k*400;
    const int cend = hh*200 + 200;

    for (int cb = hh*200 + warp*4; cb < cend; cb += 16) {
        ull w2[4][16], s2[4], c2[4];
        float cj[4];
        #pragma unroll
        for (int j = 0; j < 4; j++) {
            const int pi = i*AC + k*400 + cb + j;
            const float* wp = W2 + pi*16;
            #pragma unroll
            for (int cin = 0; cin < 16; cin++) {
                float wv = wp[cin];
                w2[j][cin] = pack2(wv, wv);
            }
            float sc = g2[pi] * rsqrtf(v2[pi] + EPSI);
            float cc = fmaf(-m2[pi], sc, b2[pi]);          // b - m*s
            cj[j] = cc;
            s2[j] = pack2(sc, sc);
            c2[j] = pack2(cc, cc);
        }

        float acc[4] = {0.f, 0.f, 0.f, 0.f};
        #pragma unroll 3
        for (int it = 0; it < 9; it++) {                   // 288 pairs / 32 lanes
            const int pp2 = (lane + it*32) * 2;
            ull d2[4] = {0ull, 0ull, 0ull, 0ull};
            #pragma unroll
            for (int cin = 0; cin < 16; cin++) {
                ull xv = *(const ull*)&tile[cin*HW + pp2]; // LDS.64, conflict-free
                #pragma unroll
                for (int j = 0; j < 4; j++)
                    d2[j] = fma2(xv, w2[j][cin], d2[j]);
            }
            #pragma unroll
            for (int j = 0; j < 4; j++) {
                ull t = fma2(d2[j], s2[j], c2[j]);         // BN, both pixels
                float lo, hi; unpack2(t, lo, hi);
                acc[j] += fmaxf(lo, 0.f) + fmaxf(hi, 0.f); // ReLU + pool accum
            }
        }
        #pragma unroll
        for (int j = 0; j < 4; j++) {
            float a = acc[j];
            #pragma unroll
            for (int off = 16; off; off >>= 1)
                a += __shfl_xor_sync(0xffffffffu, a, off);
            if (lane == 0) {
                // 100 border pixels of the (pad=1) 26x26 conv output
                float border = 100.f * fmaxf(cj[j], 0.f);
                pooled[cb + j] = (a + border) * (1.f / 676.f);
            }
        }
    }
}

// ---------------------------------------------------------------------------
// aff_i[i,b,l] = <pooled[i,b,i*400:..], pooled[i,b,l*400:..]>/16
// One warp per (i,b,l).
// ---------------------------------------------------------------------------
__global__ __launch_bounds__(256) void aff_kernel()
{
    const int gw = blockIdx.x*8 + (threadIdx.x >> 5);   // 0..511
    const int lane = threadIdx.x & 31;
    const int i = gw >> 5, b = (gw >> 4) & 1, l = gw & 15;
    const float* base = g_pooled + (i*Bsz + b)*AC;
    const float* pa = base + i*400;
    const float* pb = base + l*400;
    float s = 0.f;
    #pragma unroll
    for (int m3 = lane; m3 < 400; m3 += 32)
        s = fmaf(pa[m3], pb[m3], s);
    #pragma unroll
    for (int off = 16; off; off >>= 1)
        s += __shfl_xor_sync(0xffffffffu, s, off);
    if (lane == 0) g_aff[(i*Bsz + b)*G + l] = s * (1.f / 16.f);
}

// ---------------------------------------------------------------------------
// z[i,p,q,cg,hw] = sum_k aff_i[i,p,k] * h1[i,q,k*16+cg,hw]
// float2 pixel pairs; each thread produces both p outputs from one h1 read.
// ---------------------------------------------------------------------------
__global__ __launch_bounds__(256) void out_kernel(float2* __restrict__ out)
{
    const int idx = blockIdx.x*256 + threadIdx.x;
    if (idx >= 512*(HW/2)) return;
    const int pp2 = idx % (HW/2);             // pixel pair 0..287
    const int ch  = idx / (HW/2);             // 0..511
    const int i = ch >> 5, q = (ch >> 4) & 1, cg = ch & 15;

    const float* a0 = g_aff + (i*Bsz + 0)*G;              // warp-uniform
    const float* a1 = g_aff + (i*Bsz + 1)*G;
    const float2* h = (const float2*)(g_h1 + ((i*Bsz + q)*C + cg)*HW) + pp2;
    float2 s0 = make_float2(0.f, 0.f), s1 = make_float2(0.f, 0.f);
    #pragma unroll
    for (int kk = 0; kk < 16; kk++) {
        float2 hv = __ldg(h + kk*16*(HW/2));
        float w0 = a0[kk], w1 = a1[kk];
        s0.x = fmaf(w0, hv.x, s0.x); s0.y = fmaf(w0, hv.y, s0.y);
        s1.x = fmaf(w1, hv.x, s1.x); s1.y = fmaf(w1, hv.y, s1.y);
    }
    out[ch*(HW/2) + pp2]              = s0;   // p = 0
    out[512*(HW/2) + ch*(HW/2) + pp2] = s1;   // p = 1
}

// ---------------------------------------------------------------------------
extern "C" void kernel_launch(void* const* d_in, const int* in_sizes, int n_in,
                              void* d_out, int out_size)
{
    const float* x  = (const float*)d_in[0];
    const float* W1 = (const float*)d_in[1];
    const float* g1 = (const float*)d_in[2];
    const float* b1 = (const float*)d_in[3];
    const float* m1 = (const float*)d_in[4];
    const float* v1 = (const float*)d_in[5];
    const float* W2 = (const float*)d_in[6];
    const float* g2 = (const float*)d_in[7];
    const float* b2 = (const float*)d_in[8];
    const float* m2 = (const float*)d_in[9];
    const float* v2 = (const float*)d_in[10];
    float2* out = (float2*)d_out;

    conv1_kernel<<<1024, 192>>>(x, W1, g1, b1, m1, v1);
    conv2_pool_kernel<<<1024, 128>>>(W2, g2, b2, m2, v2);
    aff_kernel<<<64, 256>>>();
    out_kernel<<<(512*(HW/2) + 255)/256, 256>>>(out);
}